// round 2
// baseline (speedup 1.0000x reference)
#include <cuda_runtime.h>
#include <math.h>

// Problem constants (fixed by the dataset)
#define T_STEPS 1000
#define N_B     64
#define H_DIM   1024
#define C_DIM   256
#define G3      768           // 3*C
#define SCAN_BLOCKS 128
#define SCAN_THREADS 128
#define FLAG_STRIDE 32        // ints (128B) per flag to avoid same-line contention

// Scratch (allocation-free rule: __device__ globals)
__device__ float g_xpT[(size_t)T_STEPS * G3 * N_B];   // xp transposed: [t][g][n]
__device__ float g_h[C_DIM * N_B];                    // h transposed:  [c][n]
__device__ int   g_flags[SCAN_BLOCKS * FLAG_STRIDE];  // grid barrier flags

// ---------------------------------------------------------------------------
// Kernel 1: xp[t][g][n] = sum_h enc[t][n][h] * W_ih[g][h] + b_ih[g]
// Classic fp32 SGEMM, BM=64(m = n within t), BN=64(g), BK=16, 4x4 thread tile.
// Also zeroes the scan barrier flags (runs before scan every replay).
// ---------------------------------------------------------------------------
__global__ void __launch_bounds__(256) gemm_xp_kernel(const float* __restrict__ A,
                                                      const float* __restrict__ W,
                                                      const float* __restrict__ bih)
{
    if (blockIdx.x == 0 && blockIdx.y == 0 && threadIdx.x < SCAN_BLOCKS)
        g_flags[threadIdx.x * FLAG_STRIDE] = 0;

    __shared__ float As[16][68];
    __shared__ float Bs[16][68];

    const int t   = blockIdx.y;
    const int g0  = blockIdx.x * 64;
    const int tid = threadIdx.x;
    const int lr  = tid >> 2;          // 0..63 row within tile
    const int lc4 = (tid & 3) << 2;    // 0,4,8,12 k-offset
    const int tx  = tid & 15;          // g quad
    const int ty  = tid >> 4;          // m quad

    const float* Ab = A + ((size_t)t * 64 + lr) * H_DIM + lc4;
    const float* Wb = W + ((size_t)(g0 + lr)) * H_DIM + lc4;

    float acc[4][4];
    #pragma unroll
    for (int i = 0; i < 4; ++i)
        #pragma unroll
        for (int j = 0; j < 4; ++j) acc[i][j] = 0.f;

    for (int k0 = 0; k0 < H_DIM; k0 += 16) {
        float4 a = *(const float4*)(Ab + k0);
        float4 b = *(const float4*)(Wb + k0);
        As[lc4 + 0][lr] = a.x; As[lc4 + 1][lr] = a.y;
        As[lc4 + 2][lr] = a.z; As[lc4 + 3][lr] = a.w;
        Bs[lc4 + 0][lr] = b.x; Bs[lc4 + 1][lr] = b.y;
        Bs[lc4 + 2][lr] = b.z; Bs[lc4 + 3][lr] = b.w;
        __syncthreads();
        #pragma unroll
        for (int k = 0; k < 16; ++k) {
            float4 ra = *(const float4*)&As[k][ty << 2];
            float4 rb = *(const float4*)&Bs[k][tx << 2];
            float am[4] = {ra.x, ra.y, ra.z, ra.w};
            float bg[4] = {rb.x, rb.y, rb.z, rb.w};
            #pragma unroll
            for (int i = 0; i < 4; ++i)
                #pragma unroll
                for (int j = 0; j < 4; ++j)
                    acc[i][j] = fmaf(am[i], bg[j], acc[i][j]);
        }
        __syncthreads();
    }

    // Epilogue: add bias, write transposed layout xpT[t][g][n]
    #pragma unroll
    for (int j = 0; j < 4; ++j) {
        int g = g0 + (tx << 2) + j;
        float bv = __ldg(&bih[g]);
        float4 o;
        o.x = acc[0][j] + bv;
        o.y = acc[1][j] + bv;
        o.z = acc[2][j] + bv;
        o.w = acc[3][j] + bv;
        *(float4*)&g_xpT[((size_t)t * G3 + g) * N_B + (ty << 2)] = o;
    }
}

// ---------------------------------------------------------------------------
// Kernel 2: persistent GRU scan. 128 blocks x 128 threads.
// Block b owns output columns c = 2b, 2b+1 for all 64 batch rows.
// W_hh slice (6 rows x 256) cached in smem once; full h (64KB) staged per step.
// Grid barrier: per-block flag line, each thread polls one flag.
// Writes h_t to d_out as [t][c][n] (transposed scratch for the softmax pass).
// ---------------------------------------------------------------------------
__global__ void __launch_bounds__(SCAN_THREADS) scan_kernel(const float* __restrict__ Whh,
                                                            const float* __restrict__ bhh,
                                                            float* __restrict__ out)
{
    extern __shared__ float sm[];
    float* h_s = sm;                    // [256][64]
    float* W_s = sm + C_DIM * N_B;      // 6 rows x 256 (row = gate*2 + cc)

    const int tid = threadIdx.x;
    const int bid = blockIdx.x;
    const int cc  = tid >> 6;           // 0..1
    const int n   = tid & 63;           // batch row
    const int c   = bid * 2 + cc;       // output column

    // Load this block's W_hh rows (r,z,n gates for its 2 columns)
    {
        float4* Wd = (float4*)W_s;
        for (int i4 = tid; i4 < 6 * 64; i4 += SCAN_THREADS) {
            int row  = i4 >> 6;         // 0..5
            int k4   = i4 & 63;
            int gate = row >> 1;
            int ccl  = row & 1;
            Wd[i4] = ((const float4*)(Whh + ((size_t)(gate * C_DIM + bid * 2 + ccl)) * C_DIM))[k4];
        }
    }
    const float bhr = __ldg(&bhh[c]);
    const float bhz = __ldg(&bhh[C_DIM + c]);
    const float bhn = __ldg(&bhh[2 * C_DIM + c]);
    __syncthreads();

    const float4* Wr4 = (const float4*)(W_s + (0 * 2 + cc) * C_DIM);
    const float4* Wz4 = (const float4*)(W_s + (1 * 2 + cc) * C_DIM);
    const float4* Wn4 = (const float4*)(W_s + (2 * 2 + cc) * C_DIM);

    for (int t = 0; t < T_STEPS; ++t) {
        float accr = 0.f, accz = 0.f, accn = 0.f, h_old = 0.f;
        if (t > 0) {
            // Stage full h (written last step by all blocks) into smem, L1-bypassed
            const float4* hsrc = (const float4*)g_h;
            float4* hdst = (float4*)h_s;
            #pragma unroll
            for (int i = 0; i < (C_DIM * N_B / 4) / SCAN_THREADS; ++i)
                hdst[tid + i * SCAN_THREADS] = __ldcg(hsrc + tid + i * SCAN_THREADS);
            __syncthreads();
            h_old = h_s[c * N_B + n];
            #pragma unroll 8
            for (int k4 = 0; k4 < 64; ++k4) {
                float4 wr = Wr4[k4];
                float4 wz = Wz4[k4];
                float4 wn = Wn4[k4];
                const float* hp = h_s + k4 * 256 + n;   // 4 consecutive k rows
                float h0 = hp[0], h1 = hp[64], h2 = hp[128], h3 = hp[192];
                accr = fmaf(h0, wr.x, accr); accz = fmaf(h0, wz.x, accz); accn = fmaf(h0, wn.x, accn);
                accr = fmaf(h1, wr.y, accr); accz = fmaf(h1, wz.y, accz); accn = fmaf(h1, wn.y, accn);
                accr = fmaf(h2, wr.z, accr); accz = fmaf(h2, wz.z, accz); accn = fmaf(h2, wn.z, accn);
                accr = fmaf(h3, wr.w, accr); accz = fmaf(h3, wz.w, accz); accn = fmaf(h3, wn.w, accn);
            }
        }
        const float* xp = g_xpT + (size_t)t * (G3 * N_B);
        float xr = __ldg(xp + (0 * C_DIM + c) * N_B + n);
        float xz = __ldg(xp + (1 * C_DIM + c) * N_B + n);
        float xn = __ldg(xp + (2 * C_DIM + c) * N_B + n);
        float r  = 1.f / (1.f + expf(-(xr + accr + bhr)));
        float z  = 1.f / (1.f + expf(-(xz + accz + bhz)));
        float nt = tanhf(xn + r * (accn + bhn));
        float hnew = nt + z * (h_old - nt);   // (1-z)*nt + z*h_old

        __stcg(&g_h[c * N_B + n], hnew);
        out[(size_t)t * (C_DIM * N_B) + c * N_B + n] = hnew;

        if (t < T_STEPS - 1) {
            __threadfence();
            __syncthreads();
            if (tid == 0) __stcg(&g_flags[bid * FLAG_STRIDE], t + 1);
            // every thread polls one block's flag (128 threads == 128 blocks)
            const int* fp = &g_flags[tid * FLAG_STRIDE];
            while (true) {
                int v;
                asm volatile("ld.global.cg.b32 %0, [%1];" : "=r"(v) : "l"(fp) : "memory");
                if (v > t) break;
                __nanosleep(64);
            }
            __threadfence();
            __syncthreads();
        }
    }
}

// ---------------------------------------------------------------------------
// Kernel 3: log-softmax over C with in-place layout fix.
// d_out currently holds [t][c][n]; rewrite to [t][n][c] = x - max - log(sum exp).
// One block per t; full 64KB tile staged through smem (safe in-place).
// ---------------------------------------------------------------------------
__global__ void __launch_bounds__(256) logsoftmax_kernel(float* __restrict__ out)
{
    extern __shared__ float s[];      // [256][64]
    __shared__ float redm[4][64];
    __shared__ float reds[4][64];

    const int t   = blockIdx.x;
    const int tid = threadIdx.x;
    float* base = out + (size_t)t * (C_DIM * N_B);

    float4* s4 = (float4*)s;
    const float4* b4 = (const float4*)base;
    #pragma unroll
    for (int i = 0; i < (C_DIM * N_B / 4) / 256; ++i)
        s4[tid + i * 256] = b4[tid + i * 256];
    __syncthreads();

    const int n = tid & 63;
    const int q = tid >> 6;          // quarter of the C range
    float mx = -1e30f;
    #pragma unroll 8
    for (int k = 0; k < 64; ++k)
        mx = fmaxf(mx, s[(q * 64 + k) * 64 + n]);
    redm[q][n] = mx;
    __syncthreads();
    float M = fmaxf(fmaxf(redm[0][n], redm[1][n]), fmaxf(redm[2][n], redm[3][n]));
    float sum = 0.f;
    #pragma unroll 8
    for (int k = 0; k < 64; ++k)
        sum += expf(s[(q * 64 + k) * 64 + n] - M);
    reds[q][n] = sum;
    __syncthreads();
    float lse = M + logf(reds[0][n] + reds[1][n] + reds[2][n] + reds[3][n]);

    #pragma unroll
    for (int k = 0; k < 64; k += 4) {
        int cbase = q * 64 + k;
        float4 o;
        o.x = s[(cbase + 0) * 64 + n] - lse;
        o.y = s[(cbase + 1) * 64 + n] - lse;
        o.z = s[(cbase + 2) * 64 + n] - lse;
        o.w = s[(cbase + 3) * 64 + n] - lse;
        *(float4*)&base[n * C_DIM + cbase] = o;
    }
}

// ---------------------------------------------------------------------------
extern "C" void kernel_launch(void* const* d_in, const int* in_sizes, int n_in,
                              void* d_out, int out_size)
{
    const float* enc  = (const float*)d_in[0];
    const float* W_ih = (const float*)d_in[1];
    const float* W_hh = (const float*)d_in[2];
    const float* b_ih = (const float*)d_in[3];
    const float* b_hh = (const float*)d_in[4];
    float* out = (float*)d_out;

    const int scan_smem = (C_DIM * N_B + 6 * C_DIM) * (int)sizeof(float); // 71680
    const int ls_smem   = C_DIM * N_B * (int)sizeof(float);               // 65536
    cudaFuncSetAttribute(scan_kernel, cudaFuncAttributeMaxDynamicSharedMemorySize, scan_smem);
    cudaFuncSetAttribute(logsoftmax_kernel, cudaFuncAttributeMaxDynamicSharedMemorySize, ls_smem);

    gemm_xp_kernel<<<dim3(G3 / 64, T_STEPS), 256>>>(enc, W_ih, b_ih);
    scan_kernel<<<SCAN_BLOCKS, SCAN_THREADS, scan_smem>>>(W_hh, b_hh, out);
    logsoftmax_kernel<<<T_STEPS, 256, ls_smem>>>(out);
}

// round 4
// speedup vs baseline: 1.0872x; 1.0872x over previous
#include <cuda_runtime.h>
#include <math.h>
#include <stdint.h>

#define T_STEPS 1000
#define N_B     64
#define H_DIM   1024
#define C_DIM   256
#define G3      768
#define SCAN_BLOCKS 128
#define SCAN_THREADS 128
#define FLAG_STRIDE 32

__device__ float g_xpT[(size_t)T_STEPS * G3 * N_B];
__device__ float g_h[C_DIM * N_B];
__device__ int   g_flags[SCAN_BLOCKS * FLAG_STRIDE];

__device__ __forceinline__ float tf32_round(float f) {
    uint32_t r;
    asm("cvt.rna.tf32.f32 %0, %1;" : "=r"(r) : "f"(f));
    return __uint_as_float(r);
}
__device__ __forceinline__ void tf32_split(float x, float& hi, float& lo) {
    hi = tf32_round(x);
    lo = tf32_round(x - hi);
}

#define MMA_TF32(d, a, b)                                                       \
    asm volatile(                                                               \
        "mma.sync.aligned.m16n8k8.row.col.f32.tf32.tf32.f32 "                   \
        "{%0,%1,%2,%3}, {%4,%5,%6,%7}, {%8,%9}, {%0,%1,%2,%3};"                 \
        : "+f"(d[0]), "+f"(d[1]), "+f"(d[2]), "+f"(d[3])                        \
        : "r"(a[0]), "r"(a[1]), "r"(a[2]), "r"(a[3]), "r"(b[0]), "r"(b[1]))

#define BM 128
#define BN 128
#define BK 16
#define LDP 20

// ---------------------------------------------------------------------------
// Kernel 1: 3xTF32 tensor-core GEMM (fp32-accurate to ~2^-21).
// xp[t][g][n] = sum_h enc[(t,n)][h] * W_ih[g][h] + b_ih[g]
// acc += Ah*Bh + Al*Bh + Ah*Bl   (Al*Bl term negligible, skipped)
// ---------------------------------------------------------------------------
__global__ void __launch_bounds__(256) gemm_xp_tc(const float* __restrict__ A,
                                                  const float* __restrict__ W,
                                                  const float* __restrict__ bih)
{
    if (blockIdx.x == 0 && blockIdx.y == 0 && threadIdx.x < SCAN_BLOCKS)
        g_flags[threadIdx.x * FLAG_STRIDE] = 0;

    __shared__ float Ah[BM * LDP];
    __shared__ float Al[BM * LDP];
    __shared__ float Bh[BN * LDP];
    __shared__ float Bl[BN * LDP];

    const int tid  = threadIdx.x;
    const int m0   = blockIdx.y * BM;
    const int g0   = blockIdx.x * BN;
    const int warp = tid >> 5;
    const int lane = tid & 31;
    const int wm   = (warp & 1) * 64;
    const int wn   = (warp >> 1) * 32;
    const int lr_  = lane >> 2;
    const int lc_  = lane & 3;

    const int lrow = tid >> 1;
    const int lk   = (tid & 1) * 8;
    const float* Ag = A + (size_t)(m0 + lrow) * H_DIM + lk;
    const float* Wg = W + (size_t)(g0 + lrow) * H_DIM + lk;

    float4 ra0 = *(const float4*)(Ag);
    float4 ra1 = *(const float4*)(Ag + 4);
    float4 rb0 = *(const float4*)(Wg);
    float4 rb1 = *(const float4*)(Wg + 4);

    float acc[4][4][4];
    #pragma unroll
    for (int mi = 0; mi < 4; ++mi)
        #pragma unroll
        for (int ni = 0; ni < 4; ++ni)
            #pragma unroll
            for (int r = 0; r < 4; ++r) acc[mi][ni][r] = 0.f;

    for (int k0 = 0; k0 < H_DIM; k0 += BK) {
        __syncthreads();
        {
            float* aph = &Ah[lrow * LDP + lk];
            float* apl = &Al[lrow * LDP + lk];
            float av[8] = {ra0.x, ra0.y, ra0.z, ra0.w, ra1.x, ra1.y, ra1.z, ra1.w};
            #pragma unroll
            for (int i = 0; i < 8; ++i) tf32_split(av[i], aph[i], apl[i]);
            float* bph = &Bh[lrow * LDP + lk];
            float* bpl = &Bl[lrow * LDP + lk];
            float bv[8] = {rb0.x, rb0.y, rb0.z, rb0.w, rb1.x, rb1.y, rb1.z, rb1.w};
            #pragma unroll
            for (int i = 0; i < 8; ++i) tf32_split(bv[i], bph[i], bpl[i]);
        }
        __syncthreads();

        if (k0 + BK < H_DIM) {
            ra0 = *(const float4*)(Ag + k0 + BK);
            ra1 = *(const float4*)(Ag + k0 + BK + 4);
            rb0 = *(const float4*)(Wg + k0 + BK);
            rb1 = *(const float4*)(Wg + k0 + BK + 4);
        }

        #pragma unroll
        for (int kk = 0; kk < 2; ++kk) {
            const int kb = kk * 8;
            uint32_t afh[4][4], afl[4][4];
            #pragma unroll
            for (int mi = 0; mi < 4; ++mi) {
                int r = wm + mi * 16 + lr_;
                afh[mi][0] = __float_as_uint(Ah[r * LDP + kb + lc_]);
                afh[mi][1] = __float_as_uint(Ah[(r + 8) * LDP + kb + lc_]);
                afh[mi][2] = __float_as_uint(Ah[r * LDP + kb + lc_ + 4]);
                afh[mi][3] = __float_as_uint(Ah[(r + 8) * LDP + kb + lc_ + 4]);
                afl[mi][0] = __float_as_uint(Al[r * LDP + kb + lc_]);
                afl[mi][1] = __float_as_uint(Al[(r + 8) * LDP + kb + lc_]);
                afl[mi][2] = __float_as_uint(Al[r * LDP + kb + lc_ + 4]);
                afl[mi][3] = __float_as_uint(Al[(r + 8) * LDP + kb + lc_ + 4]);
            }
            uint32_t bfh[4][2], bfl[4][2];
            #pragma unroll
            for (int ni = 0; ni < 4; ++ni) {
                int cn = wn + ni * 8 + lr_;
                bfh[ni][0] = __float_as_uint(Bh[cn * LDP + kb + lc_]);
                bfh[ni][1] = __float_as_uint(Bh[cn * LDP + kb + lc_ + 4]);
                bfl[ni][0] = __float_as_uint(Bl[cn * LDP + kb + lc_]);
                bfl[ni][1] = __float_as_uint(Bl[cn * LDP + kb + lc_ + 4]);
            }
            #pragma unroll
            for (int mi = 0; mi < 4; ++mi)
                #pragma unroll
                for (int ni = 0; ni < 4; ++ni) {
                    MMA_TF32(acc[mi][ni], afl[mi], bfh[ni]);   // Al*Bh
                    MMA_TF32(acc[mi][ni], afh[mi], bfl[ni]);   // Ah*Bl
                    MMA_TF32(acc[mi][ni], afh[mi], bfh[ni]);   // Ah*Bh
                }
        }
    }

    // Epilogue: c0=(row,col) c1=(row,col+1) c2=(row+8,col) c3=(row+8,col+1)
    #pragma unroll
    for (int mi = 0; mi < 4; ++mi) {
        int row = m0 + wm + mi * 16 + lr_;
        int t   = row >> 6;
        int n   = row & 63;          // warp tile is 64-aligned: row+8 -> same t, n+8
        #pragma unroll
        for (int ni = 0; ni < 4; ++ni) {
            int col = g0 + wn + ni * 8 + 2 * lc_;
            float bv0 = __ldg(&bih[col]);
            float bv1 = __ldg(&bih[col + 1]);
            float* p0 = &g_xpT[((size_t)t * G3 + col) * N_B];
            float* p1 = &g_xpT[((size_t)t * G3 + col + 1) * N_B];
            p0[n]     = acc[mi][ni][0] + bv0;
            p1[n]     = acc[mi][ni][1] + bv1;
            p0[n + 8] = acc[mi][ni][2] + bv0;
            p1[n + 8] = acc[mi][ni][3] + bv1;
        }
    }
}

// ---------------------------------------------------------------------------
// Kernel 2: persistent GRU scan — VERBATIM the round-2 passing version.
// ---------------------------------------------------------------------------
__global__ void __launch_bounds__(SCAN_THREADS) scan_kernel(const float* __restrict__ Whh,
                                                            const float* __restrict__ bhh,
                                                            float* __restrict__ out)
{
    extern __shared__ float sm[];
    float* h_s = sm;                    // [256][64]
    float* W_s = sm + C_DIM * N_B;      // 6 rows x 256

    const int tid = threadIdx.x;
    const int bid = blockIdx.x;
    const int cc  = tid >> 6;
    const int n   = tid & 63;
    const int c   = bid * 2 + cc;

    {
        float4* Wd = (float4*)W_s;
        for (int i4 = tid; i4 < 6 * 64; i4 += SCAN_THREADS) {
            int row  = i4 >> 6;
            int k4   = i4 & 63;
            int gate = row >> 1;
            int ccl  = row & 1;
            Wd[i4] = ((const float4*)(Whh + ((size_t)(gate * C_DIM + bid * 2 + ccl)) * C_DIM))[k4];
        }
    }
    const float bhr = __ldg(&bhh[c]);
    const float bhz = __ldg(&bhh[C_DIM + c]);
    const float bhn = __ldg(&bhh[2 * C_DIM + c]);
    __syncthreads();

    const float4* Wr4 = (const float4*)(W_s + (0 * 2 + cc) * C_DIM);
    const float4* Wz4 = (const float4*)(W_s + (1 * 2 + cc) * C_DIM);
    const float4* Wn4 = (const float4*)(W_s + (2 * 2 + cc) * C_DIM);

    for (int t = 0; t < T_STEPS; ++t) {
        float accr = 0.f, accz = 0.f, accn = 0.f, h_old = 0.f;
        if (t > 0) {
            const float4* hsrc = (const float4*)g_h;
            float4* hdst = (float4*)h_s;
            #pragma unroll
            for (int i = 0; i < (C_DIM * N_B / 4) / SCAN_THREADS; ++i)
                hdst[tid + i * SCAN_THREADS] = __ldcg(hsrc + tid + i * SCAN_THREADS);
            __syncthreads();
            h_old = h_s[c * N_B + n];
            #pragma unroll 8
            for (int k4 = 0; k4 < 64; ++k4) {
                float4 wr = Wr4[k4];
                float4 wz = Wz4[k4];
                float4 wn = Wn4[k4];
                const float* hp = h_s + k4 * 256 + n;
                float h0 = hp[0], h1 = hp[64], h2 = hp[128], h3 = hp[192];
                accr = fmaf(h0, wr.x, accr); accz = fmaf(h0, wz.x, accz); accn = fmaf(h0, wn.x, accn);
                accr = fmaf(h1, wr.y, accr); accz = fmaf(h1, wz.y, accz); accn = fmaf(h1, wn.y, accn);
                accr = fmaf(h2, wr.z, accr); accz = fmaf(h2, wz.z, accz); accn = fmaf(h2, wn.z, accn);
                accr = fmaf(h3, wr.w, accr); accz = fmaf(h3, wz.w, accz); accn = fmaf(h3, wn.w, accn);
            }
        }
        const float* xp = g_xpT + (size_t)t * (G3 * N_B);
        float xr = __ldg(xp + (0 * C_DIM + c) * N_B + n);
        float xz = __ldg(xp + (1 * C_DIM + c) * N_B + n);
        float xn = __ldg(xp + (2 * C_DIM + c) * N_B + n);
        float r  = 1.f / (1.f + expf(-(xr + accr + bhr)));
        float z  = 1.f / (1.f + expf(-(xz + accz + bhz)));
        float nt = tanhf(xn + r * (accn + bhn));
        float hnew = nt + z * (h_old - nt);

        __stcg(&g_h[c * N_B + n], hnew);
        out[(size_t)t * (C_DIM * N_B) + c * N_B + n] = hnew;

        if (t < T_STEPS - 1) {
            __threadfence();
            __syncthreads();
            if (tid == 0) __stcg(&g_flags[bid * FLAG_STRIDE], t + 1);
            const int* fp = &g_flags[tid * FLAG_STRIDE];
            while (true) {
                int v;
                asm volatile("ld.global.cg.b32 %0, [%1];" : "=r"(v) : "l"(fp) : "memory");
                if (v > t) break;
                __nanosleep(64);
            }
            __threadfence();
            __syncthreads();
        }
    }
}

// ---------------------------------------------------------------------------
// Kernel 3: log-softmax + in-place transpose [t][c][n] -> [t][n][c].
// ---------------------------------------------------------------------------
__global__ void __launch_bounds__(256) logsoftmax_kernel(float* __restrict__ out)
{
    extern __shared__ float s[];
    __shared__ float redm[4][64];
    __shared__ float reds[4][64];

    const int t   = blockIdx.x;
    const int tid = threadIdx.x;
    float* base = out + (size_t)t * (C_DIM * N_B);

    float4* s4 = (float4*)s;
    const float4* b4 = (const float4*)base;
    #pragma unroll
    for (int i = 0; i < (C_DIM * N_B / 4) / 256; ++i)
        s4[tid + i * 256] = b4[tid + i * 256];
    __syncthreads();

    const int n = tid & 63;
    const int q = tid >> 6;
    float mx = -1e30f;
    #pragma unroll 8
    for (int k = 0; k < 64; ++k)
        mx = fmaxf(mx, s[(q * 64 + k) * 64 + n]);
    redm[q][n] = mx;
    __syncthreads();
    float M = fmaxf(fmaxf(redm[0][n], redm[1][n]), fmaxf(redm[2][n], redm[3][n]));
    float sum = 0.f;
    #pragma unroll 8
    for (int k = 0; k < 64; ++k)
        sum += expf(s[(q * 64 + k) * 64 + n] - M);
    reds[q][n] = sum;
    __syncthreads();
    float lse = M + logf(reds[0][n] + reds[1][n] + reds[2][n] + reds[3][n]);

    #pragma unroll
    for (int k = 0; k < 64; k += 4) {
        int cbase = q * 64 + k;
        float4 o;
        o.x = s[(cbase + 0) * 64 + n] - lse;
        o.y = s[(cbase + 1) * 64 + n] - lse;
        o.z = s[(cbase + 2) * 64 + n] - lse;
        o.w = s[(cbase + 3) * 64 + n] - lse;
        *(float4*)&base[n * C_DIM + cbase] = o;
    }
}

extern "C" void kernel_launch(void* const* d_in, const int* in_sizes, int n_in,
                              void* d_out, int out_size)
{
    const float* enc  = (const float*)d_in[0];
    const float* W_ih = (const float*)d_in[1];
    const float* W_hh = (const float*)d_in[2];
    const float* b_ih = (const float*)d_in[3];
    const float* b_hh = (const float*)d_in[4];
    float* out = (float*)d_out;

    const int scan_smem = (C_DIM * N_B + 6 * C_DIM) * (int)sizeof(float);
    const int ls_smem   = C_DIM * N_B * (int)sizeof(float);
    cudaFuncSetAttribute(scan_kernel, cudaFuncAttributeMaxDynamicSharedMemorySize, scan_smem);
    cudaFuncSetAttribute(logsoftmax_kernel, cudaFuncAttributeMaxDynamicSharedMemorySize, ls_smem);

    gemm_xp_tc<<<dim3(G3 / BN, (T_STEPS * N_B) / BM), 256>>>(enc, W_ih, b_ih);
    scan_kernel<<<SCAN_BLOCKS, SCAN_THREADS, scan_smem>>>(W_hh, b_hh, out);
    logsoftmax_kernel<<<T_STEPS, 256, ls_smem>>>(out);
}

// round 9
// speedup vs baseline: 1.8583x; 1.7092x over previous
#include <cuda_runtime.h>
#include <math.h>
#include <stdint.h>

#define T_STEPS 1000
#define N_B     64
#define H_DIM   1024
#define C_DIM   256
#define G3      768

__device__ float g_xpT[(size_t)T_STEPS * G3 * N_B];   // [t][gate*256+c][n]
__device__ float g_hEx[16 * 1024];                     // per-cluster h exchange: [cl][row][c]

__device__ __forceinline__ float tf32_round(float f) {
    uint32_t r;
    asm("cvt.rna.tf32.f32 %0, %1;" : "=r"(r) : "f"(f));
    return __uint_as_float(r);
}
__device__ __forceinline__ void tf32_split(float x, float& hi, float& lo) {
    hi = tf32_round(x);
    lo = tf32_round(x - hi);
}

#define MMA_TF32(d, a, b)                                                       \
    asm volatile(                                                               \
        "mma.sync.aligned.m16n8k8.row.col.f32.tf32.tf32.f32 "                   \
        "{%0,%1,%2,%3}, {%4,%5,%6,%7}, {%8,%9}, {%0,%1,%2,%3};"                 \
        : "+f"(d[0]), "+f"(d[1]), "+f"(d[2]), "+f"(d[3])                        \
        : "r"(a[0]), "r"(a[1]), "r"(a[2]), "r"(a[3]), "r"(b[0]), "r"(b[1]))

#define BM 128
#define BN 128
#define BK 16
#define LDP 20

// ---------------------------------------------------------------------------
// Kernel 1: 3xTF32 tensor-core GEMM — round-4 passing version (flag code removed).
// ---------------------------------------------------------------------------
__global__ void __launch_bounds__(256) gemm_xp_tc(const float* __restrict__ A,
                                                  const float* __restrict__ W,
                                                  const float* __restrict__ bih)
{
    __shared__ float Ah[BM * LDP];
    __shared__ float Al[BM * LDP];
    __shared__ float Bh[BN * LDP];
    __shared__ float Bl[BN * LDP];

    const int tid  = threadIdx.x;
    const int m0   = blockIdx.y * BM;
    const int g0   = blockIdx.x * BN;
    const int warp = tid >> 5;
    const int lane = tid & 31;
    const int wm   = (warp & 1) * 64;
    const int wn   = (warp >> 1) * 32;
    const int lr_  = lane >> 2;
    const int lc_  = lane & 3;

    const int lrow = tid >> 1;
    const int lk   = (tid & 1) * 8;
    const float* Ag = A + (size_t)(m0 + lrow) * H_DIM + lk;
    const float* Wg = W + (size_t)(g0 + lrow) * H_DIM + lk;

    float4 ra0 = *(const float4*)(Ag);
    float4 ra1 = *(const float4*)(Ag + 4);
    float4 rb0 = *(const float4*)(Wg);
    float4 rb1 = *(const float4*)(Wg + 4);

    float acc[4][4][4];
    #pragma unroll
    for (int mi = 0; mi < 4; ++mi)
        #pragma unroll
        for (int ni = 0; ni < 4; ++ni)
            #pragma unroll
            for (int r = 0; r < 4; ++r) acc[mi][ni][r] = 0.f;

    for (int k0 = 0; k0 < H_DIM; k0 += BK) {
        __syncthreads();
        {
            float* aph = &Ah[lrow * LDP + lk];
            float* apl = &Al[lrow * LDP + lk];
            float av[8] = {ra0.x, ra0.y, ra0.z, ra0.w, ra1.x, ra1.y, ra1.z, ra1.w};
            #pragma unroll
            for (int i = 0; i < 8; ++i) tf32_split(av[i], aph[i], apl[i]);
            float* bph = &Bh[lrow * LDP + lk];
            float* bpl = &Bl[lrow * LDP + lk];
            float bv[8] = {rb0.x, rb0.y, rb0.z, rb0.w, rb1.x, rb1.y, rb1.z, rb1.w};
            #pragma unroll
            for (int i = 0; i < 8; ++i) tf32_split(bv[i], bph[i], bpl[i]);
        }
        __syncthreads();

        if (k0 + BK < H_DIM) {
            ra0 = *(const float4*)(Ag + k0 + BK);
            ra1 = *(const float4*)(Ag + k0 + BK + 4);
            rb0 = *(const float4*)(Wg + k0 + BK);
            rb1 = *(const float4*)(Wg + k0 + BK + 4);
        }

        #pragma unroll
        for (int kk = 0; kk < 2; ++kk) {
            const int kb = kk * 8;
            uint32_t afh[4][4], afl[4][4];
            #pragma unroll
            for (int mi = 0; mi < 4; ++mi) {
                int r = wm + mi * 16 + lr_;
                afh[mi][0] = __float_as_uint(Ah[r * LDP + kb + lc_]);
                afh[mi][1] = __float_as_uint(Ah[(r + 8) * LDP + kb + lc_]);
                afh[mi][2] = __float_as_uint(Ah[r * LDP + kb + lc_ + 4]);
                afh[mi][3] = __float_as_uint(Ah[(r + 8) * LDP + kb + lc_ + 4]);
                afl[mi][0] = __float_as_uint(Al[r * LDP + kb + lc_]);
                afl[mi][1] = __float_as_uint(Al[(r + 8) * LDP + kb + lc_]);
                afl[mi][2] = __float_as_uint(Al[r * LDP + kb + lc_ + 4]);
                afl[mi][3] = __float_as_uint(Al[(r + 8) * LDP + kb + lc_ + 4]);
            }
            uint32_t bfh[4][2], bfl[4][2];
            #pragma unroll
            for (int ni = 0; ni < 4; ++ni) {
                int cn = wn + ni * 8 + lr_;
                bfh[ni][0] = __float_as_uint(Bh[cn * LDP + kb + lc_]);
                bfh[ni][1] = __float_as_uint(Bh[cn * LDP + kb + lc_ + 4]);
                bfl[ni][0] = __float_as_uint(Bl[cn * LDP + kb + lc_]);
                bfl[ni][1] = __float_as_uint(Bl[cn * LDP + kb + lc_ + 4]);
            }
            #pragma unroll
            for (int mi = 0; mi < 4; ++mi)
                #pragma unroll
                for (int ni = 0; ni < 4; ++ni) {
                    MMA_TF32(acc[mi][ni], afl[mi], bfh[ni]);
                    MMA_TF32(acc[mi][ni], afh[mi], bfl[ni]);
                    MMA_TF32(acc[mi][ni], afh[mi], bfh[ni]);
                }
        }
    }

    #pragma unroll
    for (int mi = 0; mi < 4; ++mi) {
        int row = m0 + wm + mi * 16 + lr_;
        int t   = row >> 6;
        int n   = row & 63;
        #pragma unroll
        for (int ni = 0; ni < 4; ++ni) {
            int col = g0 + wn + ni * 8 + 2 * lc_;
            float bv0 = __ldg(&bih[col]);
            float bv1 = __ldg(&bih[col + 1]);
            float* p0 = &g_xpT[((size_t)t * G3 + col) * N_B];
            float* p1 = &g_xpT[((size_t)t * G3 + col + 1) * N_B];
            p0[n]     = acc[mi][ni][0] + bv0;
            p1[n]     = acc[mi][ni][1] + bv1;
            p0[n + 8] = acc[mi][ni][2] + bv0;
            p1[n + 8] = acc[mi][ni][3] + bv1;
        }
    }
}

// ---------------------------------------------------------------------------
// Kernel 2: cluster-parallel GRU scan. NO software grid barrier.
// 16 clusters x 8 CTAs x 256 threads. Cluster cl owns batch rows 4cl..4cl+3
// (rows evolve independently in a GRU — only channels couple). CTA rank r
// owns output channels 32r..32r+31; its W_hh slice (3 gates x 32 ch x 256 k
// = 96KB) lives in smem as [g][k][ch] (W reads conflict-free, h broadcast).
// Per step: dot -> smem k-reduction -> gates -> store h chunk to g_hEx ->
// threadfence + HW cluster.sync -> reload full 4KB h slice. Deterministic
// and race-free by construction.
// ---------------------------------------------------------------------------
#define CL_CTAS 8
#define SCAN_THR 256
// smem floats: W 3*256*32 = 24576 | h 4*256 = 1024 | red 256*12 = 3072
#define W_FLOATS   24576
#define H_FLOATS   1024
#define RED_FLOATS 3072
#define SCAN_SMEM_BYTES ((W_FLOATS + H_FLOATS + RED_FLOATS) * 4)

#define CLUSTER_SYNC() do {                                          \
    asm volatile("barrier.cluster.arrive.aligned;" ::: "memory");    \
    asm volatile("barrier.cluster.wait.aligned;" ::: "memory");      \
} while (0)

__global__ void __launch_bounds__(SCAN_THR, 1) __cluster_dims__(CL_CTAS, 1, 1)
scan_cluster(const float* __restrict__ Whh,
             const float* __restrict__ bhh,
             float* __restrict__ out)
{
    extern __shared__ float sm[];
    float* W_s = sm;                    // [3][256][32]  (g, k, ch)
    float* h_s = sm + W_FLOATS;         // [4][256]      (row, k)
    float* red = h_s + H_FLOATS;        // [256][12]     (writer tid, row*3+g)

    const int tid  = threadIdx.x;
    const int cl   = blockIdx.x >> 3;   // cluster id 0..15
    const int rank = blockIdx.x & 7;    // CTA rank 0..7
    const int chl  = tid & 31;          // dot role: local channel
    const int ks   = tid >> 5;          // dot role: k-chunk 0..7 (k = 32*ks..)

    // reducer role (tid < 128): (rrow, rchl)
    const int rrow = tid >> 5;          // 0..3 for tid<128
    const int rchl = tid & 31;
    const int c_g  = rank * 32 + rchl;  // global channel
    const int n_g  = cl * 4 + rrow;     // global batch row

    // ---- load W slice: W_s[(g*256+k)*32 + chl] = Whh[(g*256 + rank*32 + chl)*256 + k]
    for (int idx = tid; idx < W_FLOATS; idx += SCAN_THR) {
        int lchl = idx & 31;
        int k    = (idx >> 5) & 255;
        int g    = idx >> 13;
        W_s[idx] = __ldg(&Whh[((size_t)(g * C_DIM + rank * 32 + lchl)) * C_DIM + k]);
    }
    // ---- zero h (t=0 state)
    #pragma unroll
    for (int i = 0; i < H_FLOATS / SCAN_THR; ++i)
        h_s[tid + i * SCAN_THR] = 0.f;

    float bhr = 0.f, bhz = 0.f, bhn = 0.f;
    if (tid < 128) {
        bhr = __ldg(&bhh[c_g]);
        bhz = __ldg(&bhh[C_DIM + c_g]);
        bhn = __ldg(&bhh[2 * C_DIM + c_g]);
    }
    __syncthreads();

    const int k0 = ks * 32;

    for (int t = 0; t < T_STEPS; ++t) {
        // prefetch xp gates for this step (reducer threads), overlaps the dot
        float xr = 0.f, xz = 0.f, xn = 0.f;
        if (tid < 128) {
            const float* xp = g_xpT + (size_t)t * (G3 * N_B);
            xr = __ldg(xp + (0 * C_DIM + c_g) * N_B + n_g);
            xz = __ldg(xp + (1 * C_DIM + c_g) * N_B + n_g);
            xn = __ldg(xp + (2 * C_DIM + c_g) * N_B + n_g);
        }

        // ---- partial dot over own k-chunk: acc[row][gate]
        float acc[4][3];
        #pragma unroll
        for (int rw = 0; rw < 4; ++rw)
            #pragma unroll
            for (int g = 0; g < 3; ++g) acc[rw][g] = 0.f;

        #pragma unroll
        for (int kk = 0; kk < 32; kk += 4) {
            const int k = k0 + kk;
            float4 h0 = *(const float4*)&h_s[0 * 256 + k];   // broadcast
            float4 h1 = *(const float4*)&h_s[1 * 256 + k];
            float4 h2 = *(const float4*)&h_s[2 * 256 + k];
            float4 h3 = *(const float4*)&h_s[3 * 256 + k];
            const float hv[4][4] = {
                {h0.x, h0.y, h0.z, h0.w},
                {h1.x, h1.y, h1.z, h1.w},
                {h2.x, h2.y, h2.z, h2.w},
                {h3.x, h3.y, h3.z, h3.w}};
            #pragma unroll
            for (int g = 0; g < 3; ++g) {
                const float* wp = &W_s[((g * 256 + k) << 5) + chl];
                #pragma unroll
                for (int q = 0; q < 4; ++q) {
                    float w = wp[q << 5];                     // conflict-free
                    acc[0][g] = fmaf(hv[0][q], w, acc[0][g]);
                    acc[1][g] = fmaf(hv[1][q], w, acc[1][g]);
                    acc[2][g] = fmaf(hv[2][q], w, acc[2][g]);
                    acc[3][g] = fmaf(hv[3][q], w, acc[3][g]);
                }
            }
        }

        // ---- write partials
        {
            float* rp = &red[tid * 12];
            #pragma unroll
            for (int rw = 0; rw < 4; ++rw)
                #pragma unroll
                for (int g = 0; g < 3; ++g) rp[rw * 3 + g] = acc[rw][g];
        }
        __syncthreads();

        // ---- reduce over 8 k-chunks + gates (tid < 128: one (row, ch) each)
        if (tid < 128) {
            float sr = 0.f, sz = 0.f, sn = 0.f;
            #pragma unroll
            for (int kq = 0; kq < 8; ++kq) {
                const float* rp = &red[((kq << 5) + rchl) * 12 + rrow * 3];
                sr += rp[0];
                sz += rp[1];
                sn += rp[2];
            }
            float h_old = h_s[rrow * 256 + c_g];

            float r  = 1.f / (1.f + expf(-(xr + sr + bhr)));
            float z  = 1.f / (1.f + expf(-(xz + sz + bhz)));
            float nt = tanhf(xn + r * (sn + bhn));
            float hnew = nt + z * (h_old - nt);

            __stcg(&g_hEx[cl * 1024 + rrow * 256 + c_g], hnew);
            out[(size_t)t * (C_DIM * N_B) + c_g * N_B + n_g] = hnew;
        }

        // ---- exchange: HW cluster barrier, then reload full h slice
        __threadfence();
        CLUSTER_SYNC();
        if (t < T_STEPS - 1) {
            #pragma unroll
            for (int i = 0; i < H_FLOATS / SCAN_THR; ++i)
                h_s[tid + i * SCAN_THR] = __ldcg(&g_hEx[cl * 1024 + tid + i * SCAN_THR]);
            __syncthreads();
        }
    }
}

// ---------------------------------------------------------------------------
// Kernel 3: log-softmax + in-place transpose [t][c][n] -> [t][n][c].
// ---------------------------------------------------------------------------
__global__ void __launch_bounds__(256) logsoftmax_kernel(float* __restrict__ out)
{
    extern __shared__ float s[];
    __shared__ float redm[4][64];
    __shared__ float reds[4][64];

    const int t   = blockIdx.x;
    const int tid = threadIdx.x;
    float* base = out + (size_t)t * (C_DIM * N_B);

    float4* s4 = (float4*)s;
    const float4* b4 = (const float4*)base;
    #pragma unroll
    for (int i = 0; i < (C_DIM * N_B / 4) / 256; ++i)
        s4[tid + i * 256] = b4[tid + i * 256];
    __syncthreads();

    const int n = tid & 63;
    const int q = tid >> 6;
    float mx = -1e30f;
    #pragma unroll 8
    for (int k = 0; k < 64; ++k)
        mx = fmaxf(mx, s[(q * 64 + k) * 64 + n]);
    redm[q][n] = mx;
    __syncthreads();
    float M = fmaxf(fmaxf(redm[0][n], redm[1][n]), fmaxf(redm[2][n], redm[3][n]));
    float sum = 0.f;
    #pragma unroll 8
    for (int k = 0; k < 64; ++k)
        sum += expf(s[(q * 64 + k) * 64 + n] - M);
    reds[q][n] = sum;
    __syncthreads();
    float lse = M + logf(reds[0][n] + reds[1][n] + reds[2][n] + reds[3][n]);

    #pragma unroll
    for (int k = 0; k < 64; k += 4) {
        int cbase = q * 64 + k;
        float4 o;
        o.x = s[(cbase + 0) * 64 + n] - lse;
        o.y = s[(cbase + 1) * 64 + n] - lse;
        o.z = s[(cbase + 2) * 64 + n] - lse;
        o.w = s[(cbase + 3) * 64 + n] - lse;
        *(float4*)&base[n * C_DIM + cbase] = o;
    }
}

extern "C" void kernel_launch(void* const* d_in, const int* in_sizes, int n_in,
                              void* d_out, int out_size)
{
    const float* enc  = (const float*)d_in[0];
    const float* W_ih = (const float*)d_in[1];
    const float* W_hh = (const float*)d_in[2];
    const float* b_ih = (const float*)d_in[3];
    const float* b_hh = (const float*)d_in[4];
    float* out = (float*)d_out;

    const int ls_smem = C_DIM * N_B * (int)sizeof(float);   // 65536
    cudaFuncSetAttribute(scan_cluster, cudaFuncAttributeMaxDynamicSharedMemorySize, SCAN_SMEM_BYTES);
    cudaFuncSetAttribute(logsoftmax_kernel, cudaFuncAttributeMaxDynamicSharedMemorySize, ls_smem);

    gemm_xp_tc<<<dim3(G3 / BN, (T_STEPS * N_B) / BM), 256>>>(enc, W_ih, b_ih);
    scan_cluster<<<128, SCAN_THR, SCAN_SMEM_BYTES>>>(W_hh, b_hh, out);
    logsoftmax_kernel<<<T_STEPS, 256, ls_smem>>>(out);
}